// round 1
// baseline (speedup 1.0000x reference)
#include <cuda_runtime.h>
#include <stdint.h>

#define N_ROWS 32768
#define KCODES 1024
#define DDIM   256

#define Q_ELEMS 8388608LL      // 32*256*32*32
#define E_ELEMS 33554432LL     // 32768*1024
#define I_ELEMS 32768LL

__device__ float g_ee[KCODES];
__device__ float g_xx[N_ROWS];
__device__ int   g_idx[N_ROWS];
__device__ float g_partial[8192];

// ---------------------------------------------------------------------------
// ||e_k||^2 per code, fp64 accumulate. One warp per code.
// ---------------------------------------------------------------------------
__global__ void k_ee(const float* __restrict__ cb) {
    int code = blockIdx.x * 8 + (threadIdx.x >> 5);
    int lane = threadIdx.x & 31;
    const float* row = cb + code * DDIM;
    double s = 0.0;
#pragma unroll
    for (int i = 0; i < 8; i++) {
        float v = row[lane + i * 32];
        s += (double)v * (double)v;
    }
#pragma unroll
    for (int m = 16; m; m >>= 1)
        s += __shfl_xor_sync(0xffffffffu, s, m);
    if (lane == 0) g_ee[code] = (float)s;
}

// ---------------------------------------------------------------------------
// ||x_n||^2 per row, fp64 accumulate. x is [B=32, C=256, H=32, W=32].
// Row n = b*1024 + hw, element c at x[b*262144 + c*1024 + hw].
// One thread per row; warp loads are coalesced over hw.
// ---------------------------------------------------------------------------
__global__ void k_xx(const float* __restrict__ x) {
    int n = blockIdx.x * 256 + threadIdx.x;
    int b = n >> 10, hw = n & 1023;
    const float* base = x + (size_t)b * 262144 + hw;
    double s = 0.0;
#pragma unroll 4
    for (int c = 0; c < 256; c++) {
        float v = base[(size_t)c * 1024];
        s += (double)v * (double)v;
    }
    g_xx[n] = (float)s;
}

// ---------------------------------------------------------------------------
// Fused distance GEMM + argmin.
// Block: 256 threads (16x16), tile = 128 rows x 128 codes, D chunk = 16.
// Each thread: 8x8 micro-tile. Loops all 8 code tiles, keeps running
// per-row (min, idx) with ties -> lowest index (matches jnp.argmin).
// d = (xx + ee) - 2*dot  -- same fp32 expression order as reference.
// ---------------------------------------------------------------------------
__global__ __launch_bounds__(256, 2) void k_dist(const float* __restrict__ x,
                                                 const float* __restrict__ cb) {
    __shared__ float As[16][128];
    __shared__ float Bs[16][132];   // padded: stride 132 floats (16B-aligned rows)
    __shared__ float bestv[128];
    __shared__ int   besti[128];

    int tid = threadIdx.x;
    int tx = tid & 15, ty = tid >> 4;
    int n0 = blockIdx.x * 128;
    int b = n0 >> 10, hw0 = n0 & 1023;
    const float* xbase = x + (size_t)b * 262144 + hw0;

    if (tid < 128) { bestv[tid] = 3.4e38f; besti[tid] = 0x7fffffff; }

    for (int k0 = 0; k0 < KCODES; k0 += 128) {
        float acc[8][8];
#pragma unroll
        for (int i = 0; i < 8; i++)
#pragma unroll
            for (int j = 0; j < 8; j++) acc[i][j] = 0.0f;

        for (int c0 = 0; c0 < DDIM; c0 += 16) {
            __syncthreads();
            // A tile: 128 rows x 16 dims, stored [d][row]
#pragma unroll
            for (int i = 0; i < 8; i++) {
                int e = tid + i * 256;
                int c = e >> 7, n = e & 127;
                As[c][n] = xbase[(size_t)(c0 + c) * 1024 + n];
            }
            // B tile: 128 codes x 16 dims, stored [d][code] (padded)
#pragma unroll
            for (int i = 0; i < 8; i++) {
                int e = tid + i * 256;
                int code = e >> 4, d = e & 15;
                Bs[d][code] = cb[(size_t)(k0 + code) * 256 + c0 + d];
            }
            __syncthreads();
#pragma unroll
            for (int d = 0; d < 16; d++) {
                float4 a0 = *(const float4*)(&As[d][ty * 4]);
                float4 a1 = *(const float4*)(&As[d][64 + ty * 4]);
                float4 b0 = *(const float4*)(&Bs[d][tx * 4]);
                float4 b1 = *(const float4*)(&Bs[d][64 + tx * 4]);
                float av[8] = {a0.x, a0.y, a0.z, a0.w, a1.x, a1.y, a1.z, a1.w};
                float bv[8] = {b0.x, b0.y, b0.z, b0.w, b1.x, b1.y, b1.z, b1.w};
#pragma unroll
                for (int i = 0; i < 8; i++)
#pragma unroll
                    for (int j = 0; j < 8; j++)
                        acc[i][j] = fmaf(av[i], bv[j], acc[i][j]);
            }
        }

        // Epilogue for this code tile: distances + running argmin.
        float xr[8], ec[8];
        int rows[8], cols[8];
#pragma unroll
        for (int i = 0; i < 8; i++) {
            int r = (i < 4) ? (ty * 4 + i) : (64 + ty * 4 + (i - 4));
            rows[i] = r;
            xr[i] = g_xx[n0 + r];
        }
#pragma unroll
        for (int j = 0; j < 8; j++) {
            int c = (j < 4) ? (tx * 4 + j) : (64 + tx * 4 + (j - 4));
            cols[j] = k0 + c;
            ec[j] = g_ee[k0 + c];
        }
#pragma unroll
        for (int i = 0; i < 8; i++) {
            float bv2 = 3.4e38f;
            int bi = 0x7fffffff;
#pragma unroll
            for (int j = 0; j < 8; j++) {
                float dd = (xr[i] + ec[j]) - 2.0f * acc[i][j];
                if (dd < bv2 || (dd == bv2 && cols[j] < bi)) { bv2 = dd; bi = cols[j]; }
            }
            // reduce across tx (16 lanes; xor masks stay inside 16-lane halves)
#pragma unroll
            for (int m = 8; m; m >>= 1) {
                float ov = __shfl_xor_sync(0xffffffffu, bv2, m);
                int oi = __shfl_xor_sync(0xffffffffu, bi, m);
                if (ov < bv2 || (ov == bv2 && oi < bi)) { bv2 = ov; bi = oi; }
            }
            if (tx == 0) {
                int r = rows[i];
                if (bv2 < bestv[r] || (bv2 == bestv[r] && bi < besti[r])) {
                    bestv[r] = bv2; besti[r] = bi;
                }
            }
        }
    }
    __syncthreads();
    if (tid < 128) g_idx[n0 + tid] = besti[tid];
}

// ---------------------------------------------------------------------------
// Quantized output (straight-through, literal fp32 ops) + per-block SSE.
// t indexes the output layout [B,C,H,W] which equals x's layout.
// 8192 blocks x 256 threads x 4 elems = 8,388,608.
// ---------------------------------------------------------------------------
__global__ void k_quant(const float* __restrict__ x, const float* __restrict__ cb,
                        float* __restrict__ outq, int enable_q) {
    long long t0 = (long long)blockIdx.x * 1024;
    float local = 0.0f;
#pragma unroll
    for (int i = 0; i < 4; i++) {
        long long t = t0 + threadIdx.x + i * 256;
        int bb = (int)(t >> 18);
        int rem = (int)(t & 262143);
        int c = rem >> 10, hw = rem & 1023;
        int n = (bb << 10) + hw;
        int idx = g_idx[n];
        float q = cb[(size_t)idx * 256 + c];
        float in = x[t];
        float diff = q - in;                 // (quantized - inputs), fp32
        if (enable_q) outq[t] = in + diff;   // inputs + (q - i)
        local = fmaf(diff, diff, local);
    }
    __shared__ float red[256];
    red[threadIdx.x] = local;
    __syncthreads();
    for (int s = 128; s; s >>= 1) {
        if (threadIdx.x < s) red[threadIdx.x] += red[threadIdx.x + s];
        __syncthreads();
    }
    if (threadIdx.x == 0) g_partial[blockIdx.x] = red[0];
}

// Fixed-order final loss reduction.
__global__ void k_loss(float* __restrict__ out_loss) {
    __shared__ float red[256];
    float s = 0.0f;
    int base = threadIdx.x * 32;
#pragma unroll
    for (int i = 0; i < 32; i++) s += g_partial[base + i];
    red[threadIdx.x] = s;
    __syncthreads();
    for (int t = 128; t; t >>= 1) {
        if (threadIdx.x < t) red[threadIdx.x] += red[threadIdx.x + t];
        __syncthreads();
    }
    if (threadIdx.x == 0) {
        float m = red[0] / 8388608.0f;       // both latent losses equal this
        out_loss[0] = m + 0.25f * m;         // q_latent + 0.25 * e_latent
    }
}

// One-hot set + indices-as-float.
__global__ void k_onehot(float* __restrict__ enc, float* __restrict__ outi,
                         int enable_e, int enable_i) {
    int n = blockIdx.x * 256 + threadIdx.x;
    int idx = g_idx[n];
    if (enable_e) enc[(long long)n * 1024 + idx] = 1.0f;
    if (enable_i) outi[n] = (float)idx;
}

// ---------------------------------------------------------------------------
extern "C" void kernel_launch(void* const* d_in, const int* in_sizes, int n_in,
                              void* d_out, int out_size) {
    const float* x  = (const float*)d_in[0];
    const float* cb = (const float*)d_in[1];
    // robustness: swap if metadata order differs
    if (n_in >= 2 && in_sizes[0] == KCODES * DDIM && in_sizes[1] == (int)Q_ELEMS) {
        const float* t = x; x = cb; cb = t;
    }
    float* out = (float*)d_out;

    long long os = (long long)out_size;
    long long off_loss = -1, off_q = -1, off_e = -1, off_i = -1;
    if (os == 1 + Q_ELEMS + E_ELEMS + I_ELEMS) {
        off_loss = 0; off_q = 1; off_e = 1 + Q_ELEMS; off_i = 1 + Q_ELEMS + E_ELEMS;
    } else if (os == Q_ELEMS) {
        off_q = 0;
    } else if (os == 1) {
        off_loss = 0;
    } else if (os == 1 + Q_ELEMS) {
        off_loss = 0; off_q = 1;
    } else {
        // prefix fallback in reference return order
        if (os >= 1) off_loss = 0;
        if (os >= 1 + Q_ELEMS) off_q = 1;
        if (os >= 1 + Q_ELEMS + E_ELEMS) off_e = 1 + Q_ELEMS;
        if (os >= 1 + Q_ELEMS + E_ELEMS + I_ELEMS) off_i = 1 + Q_ELEMS + E_ELEMS;
    }

    k_ee<<<128, 256>>>(cb);
    k_xx<<<128, 256>>>(x);
    k_dist<<<256, 256>>>(x, cb);

    k_quant<<<8192, 256>>>(x, cb,
                           (off_q >= 0) ? (out + off_q) : out,
                           (off_q >= 0) ? 1 : 0);
    if (off_loss >= 0) k_loss<<<1, 256>>>(out + off_loss);

    if (off_e >= 0)
        cudaMemsetAsync(out + off_e, 0, (size_t)E_ELEMS * sizeof(float));
    k_onehot<<<128, 256>>>((off_e >= 0) ? (out + off_e) : out,
                           (off_i >= 0) ? (out + off_i) : out,
                           (off_e >= 0) ? 1 : 0,
                           (off_i >= 0) ? 1 : 0);
}

// round 4
// speedup vs baseline: 1.1736x; 1.1736x over previous
#include <cuda_runtime.h>
#include <cuda_bf16.h>
#include <stdint.h>

#define N_ROWS 32768
#define KCODES 1024
#define DDIM   256

#define Q_ELEMS 8388608LL      // 32*256*32*32
#define E_ELEMS 33554432LL     // 32768*1024
#define I_ELEMS 32768LL

__device__ float g_ee[KCODES];
__device__ float g_xx[N_ROWS];
__device__ int   g_idx[N_ROWS];
__device__ float g_partial[8192];
__device__ __align__(16) __nv_bfloat16 g_X1[N_ROWS * DDIM];
__device__ __align__(16) __nv_bfloat16 g_X2[N_ROWS * DDIM];
__device__ __align__(16) __nv_bfloat16 g_E1[KCODES * DDIM];
__device__ __align__(16) __nv_bfloat16 g_E2[KCODES * DDIM];
__device__ __align__(16) float g_XT[N_ROWS * DDIM];       // exact fp32, row-major
__device__ __align__(16) float g_D[(size_t)N_ROWS * KCODES]; // approx distances

// ======================= baseline-PTX helpers ==============================
__device__ __forceinline__ uint32_t smem_u32(const void* p) {
    uint32_t a;
    asm("{ .reg .u64 t; cvta.to.shared.u64 t, %1; cvt.u32.u64 %0, t; }" : "=r"(a) : "l"(p));
    return a;
}
#define CP16(dst, src) \
    asm volatile("cp.async.cg.shared.global [%0], [%1], 16;" :: "r"(dst), "l"(src))
#define CP_COMMIT() asm volatile("cp.async.commit_group;" ::: "memory")

#define LDSM4(r, a) \
    asm volatile("ldmatrix.sync.aligned.m8n8.x4.shared.b16 {%0,%1,%2,%3}, [%4];" \
        : "=r"((r)[0]), "=r"((r)[1]), "=r"((r)[2]), "=r"((r)[3]) : "r"(a))

#define MMA16816(d, a, b0v, b1v) \
    asm volatile("mma.sync.aligned.m16n8k16.row.col.f32.bf16.bf16.f32 " \
        "{%0,%1,%2,%3}, {%4,%5,%6,%7}, {%8,%9}, {%0,%1,%2,%3};" \
        : "+f"((d)[0]), "+f"((d)[1]), "+f"((d)[2]), "+f"((d)[3]) \
        : "r"((a)[0]), "r"((a)[1]), "r"((a)[2]), "r"((a)[3]), "r"(b0v), "r"(b1v))

// ======================= precompute kernels ================================
__global__ void k_ee(const float* __restrict__ cb) {
    int code = blockIdx.x * 8 + (threadIdx.x >> 5);
    int lane = threadIdx.x & 31;
    const float* row = cb + code * DDIM;
    double s = 0.0;
#pragma unroll
    for (int i = 0; i < 8; i++) { float v = row[lane + i * 32]; s += (double)v * v; }
#pragma unroll
    for (int m = 16; m; m >>= 1) s += __shfl_xor_sync(0xffffffffu, s, m);
    if (lane == 0) g_ee[code] = (float)s;
}

__global__ void k_xx(const float* __restrict__ x) {
    int n = blockIdx.x * 256 + threadIdx.x;
    int b = n >> 10, hw = n & 1023;
    const float* base = x + (size_t)b * 262144 + hw;
    double s = 0.0;
#pragma unroll 4
    for (int c = 0; c < 256; c++) { float v = base[(size_t)c * 1024]; s += (double)v * v; }
    g_xx[n] = (float)s;
}

// transpose + fp32 copy + 2-way bf16 split of x: [B,C,H,W] -> [n][d]
__global__ void k_splitx(const float* __restrict__ x) {
    __shared__ float s[32][33];
    int bid = blockIdx.x;
    int b = bid >> 8, ct = (bid >> 5) & 7, ht = bid & 31;
    int tx = threadIdx.x & 31, ty = threadIdx.x >> 5;
#pragma unroll
    for (int r = 0; r < 4; r++)
        s[ty + r * 8][tx] = x[(((size_t)b * 256 + ct * 32 + ty + r * 8) << 10) + ht * 32 + tx];
    __syncthreads();
#pragma unroll
    for (int r = 0; r < 4; r++) {
        int hwl = ty + r * 8;
        int n = (b << 10) + ht * 32 + hwl;
        float v = s[tx][hwl];
        __nv_bfloat16 h1 = __float2bfloat16(v);
        float v2 = v - __bfloat162float(h1);
        g_XT[(size_t)n * 256 + ct * 32 + tx] = v;
        g_X1[(size_t)n * 256 + ct * 32 + tx] = h1;
        g_X2[(size_t)n * 256 + ct * 32 + tx] = __float2bfloat16(v2);
    }
}

__global__ void k_splite(const float* __restrict__ cb) {
    int i = blockIdx.x * 256 + threadIdx.x;
    float v = cb[i];
    __nv_bfloat16 h1 = __float2bfloat16(v);
    g_E1[i] = h1;
    g_E2[i] = __float2bfloat16(v - __bfloat162float(h1));
}

// ======================= HMMA distance GEMM ================================
// smem: 3 stages of (A 128x80B | B 128x80B), es[1024], xs[128]
#define STG_BYTES 20480
#define SM_ES 61440
#define SM_XS 65536
#define DIST_SMEM 66048

__device__ __forceinline__ void issue_chunk(char* smem, int s, int c, int nb,
                                            int n0, int tid) {
    int p = c >> 3, kc = c & 7;
    const __nv_bfloat16* Ab = (p < 2) ? g_X1 : g_X2;
    const __nv_bfloat16* Bb = (p == 1) ? g_E2 : g_E1;
    char* stA = smem + s * STG_BYTES;
    char* stB = stA + 10240;
#pragma unroll
    for (int it = 0; it < 2; it++) {
        int idx = tid + it * 256;
        int r = idx >> 2, g = idx & 3;
        uint32_t da = smem_u32(stA + r * 80 + g * 16);
        CP16(da, Ab + (size_t)(n0 + r) * 256 + kc * 32 + g * 8);
        uint32_t db = smem_u32(stB + r * 80 + g * 16);
        CP16(db, Bb + (size_t)(nb * 128 + r) * 256 + kc * 32 + g * 8);
    }
    CP_COMMIT();
}

__global__ void __launch_bounds__(256, 1) k_dist_mma() {
    extern __shared__ char smem[];
    float* es = (float*)(smem + SM_ES);
    float* xs = (float*)(smem + SM_XS);

    int tid = threadIdx.x, lane = tid & 31, wid = tid >> 5;
    int warp_m = wid & 1, warp_n = wid >> 1;
    int n0 = blockIdx.x * 128;

    for (int i = tid; i < KCODES; i += 256) es[i] = g_ee[i];
    if (tid < 128) xs[tid] = g_xx[n0 + tid];
    __syncthreads();

    uint32_t smem0 = smem_u32(smem);
    uint32_t a_off = (uint32_t)((warp_m * 64 + (lane & 15)) * 80 + (lane >> 4) * 16);
    uint32_t b_off = (uint32_t)(10240 + (warp_n * 32 + (lane & 7)) * 80 + (lane >> 3) * 16);

    int gq = lane >> 2, iq = lane & 3;

    for (int nb = 0; nb < 8; nb++) {
        float acc[4][4][4];
#pragma unroll
        for (int mt = 0; mt < 4; mt++)
#pragma unroll
            for (int nt = 0; nt < 4; nt++)
#pragma unroll
                for (int q = 0; q < 4; q++) acc[mt][nt][q] = 0.0f;

        issue_chunk(smem, 0, 0, nb, n0, tid);
        issue_chunk(smem, 1, 1, nb, n0, tid);

        int s = 0;
        for (int c = 0; c < 24; c++) {
            if (c + 2 < 24) {
                int s2 = s + 2; if (s2 >= 3) s2 -= 3;
                issue_chunk(smem, s2, c + 2, nb, n0, tid);
            }
            if (c < 22)      asm volatile("cp.async.wait_group 2;" ::: "memory");
            else if (c < 23) asm volatile("cp.async.wait_group 1;" ::: "memory");
            else             asm volatile("cp.async.wait_group 0;" ::: "memory");
            __syncthreads();

            uint32_t stA = smem0 + s * STG_BYTES;
            uint32_t bfr[4][4];
#pragma unroll
            for (int nt = 0; nt < 4; nt++)
                LDSM4(bfr[nt], stA + b_off + nt * (8 * 80));
#pragma unroll
            for (int ks = 0; ks < 2; ks++) {
                uint32_t afr[4][4];
#pragma unroll
                for (int mt = 0; mt < 4; mt++)
                    LDSM4(afr[mt], stA + a_off + mt * (16 * 80) + ks * 32);
#pragma unroll
                for (int mt = 0; mt < 4; mt++)
#pragma unroll
                    for (int nt = 0; nt < 4; nt++)
                        MMA16816(acc[mt][nt], afr[mt], bfr[nt][ks * 2], bfr[nt][ks * 2 + 1]);
            }
            __syncthreads();
            s++; if (s >= 3) s -= 3;
        }

        // epilogue: store approximate snapped distances
#pragma unroll
        for (int mt = 0; mt < 4; mt++) {
#pragma unroll
            for (int h = 0; h < 2; h++) {
                int mrow = warp_m * 64 + mt * 16 + gq + h * 8;
                float xv = xs[mrow];
                size_t base = (size_t)(n0 + mrow) * 1024;
#pragma unroll
                for (int nt = 0; nt < 4; nt++) {
                    int nbase = nb * 128 + warp_n * 32 + nt * 8 + 2 * iq;
                    float d0 = (xv + es[nbase])     - 2.0f * acc[mt][nt][h * 2 + 0];
                    float d1 = (xv + es[nbase + 1]) - 2.0f * acc[mt][nt][h * 2 + 1];
                    *(float2*)(g_D + base + nbase) = make_float2(d0, d1);
                }
            }
        }
    }
}

// ======================= exact rescoring of near-ties ======================
#define TAU 1e-4f
__global__ void __launch_bounds__(256) k_refine(const float* __restrict__ cb) {
    int row = blockIdx.x * 8 + (threadIdx.x >> 5);
    int lane = threadIdx.x & 31;
    const float* Dr = g_D + (size_t)row * 1024;

    float m = 3.4e38f;
#pragma unroll 8
    for (int i = 0; i < 32; i++) m = fminf(m, Dr[lane + 32 * i]);
#pragma unroll
    for (int s = 16; s; s >>= 1) m = fminf(m, __shfl_xor_sync(0xffffffffu, m, s));
    float thr = m + TAU;

    const float4* xr4 = (const float4*)(g_XT + (size_t)row * 256 + lane * 8);
    float4 xa = xr4[0], xb = xr4[1];
    float xx = g_xx[row];

    float best = 3.4e38f;
    int bidx = 0x7fffffff;
    for (int i = 0; i < 32; i++) {
        float d = Dr[lane + 32 * i];
        unsigned ball = __ballot_sync(0xffffffffu, d <= thr);
        while (ball) {
            int src = __ffs(ball) - 1;
            ball &= ball - 1;
            int k = src + 32 * i;
            const float4* cr = (const float4*)(cb + (size_t)k * 256 + lane * 8);
            float4 ca = cr[0], cbv = cr[1];
            float p = xa.x * ca.x;
            p = fmaf(xa.y, ca.y, p);
            p = fmaf(xa.z, ca.z, p);
            p = fmaf(xa.w, ca.w, p);
            p = fmaf(xb.x, cbv.x, p);
            p = fmaf(xb.y, cbv.y, p);
            p = fmaf(xb.z, cbv.z, p);
            p = fmaf(xb.w, cbv.w, p);
#pragma unroll
            for (int s = 16; s; s >>= 1) p += __shfl_xor_sync(0xffffffffu, p, s);
            float dd = (xx + g_ee[k]) - 2.0f * p;
            if (dd < best || (dd == best && k < bidx)) { best = dd; bidx = k; }
        }
    }
    if (lane == 0) g_idx[row] = bidx;
}

// ======================= outputs ==========================================
__global__ void k_quant2(const float* __restrict__ x, const float* __restrict__ cb,
                         float* __restrict__ outq, int en) {
    __shared__ float xs[32][33];
    __shared__ float qs[32][33];
    __shared__ int ids[32];
    int bid = blockIdx.x;
    int b = bid >> 8, ct = (bid >> 5) & 7, ht = bid & 31;
    int tx = threadIdx.x & 31, ty = threadIdx.x >> 5;
    if (threadIdx.x < 32) ids[threadIdx.x] = g_idx[(b << 10) + ht * 32 + threadIdx.x];
#pragma unroll
    for (int r = 0; r < 4; r++)
        xs[ty + r * 8][tx] = x[(((size_t)b * 256 + ct * 32 + ty + r * 8) << 10) + ht * 32 + tx];
    __syncthreads();
#pragma unroll
    for (int r = 0; r < 4; r++) {
        int nl = ty + r * 8;
        qs[tx][nl] = cb[(size_t)ids[nl] * 256 + ct * 32 + tx];
    }
    __syncthreads();
    float local = 0.0f;
#pragma unroll
    for (int r = 0; r < 4; r++) {
        int cl = ty + r * 8;
        float in = xs[cl][tx];
        float q = qs[cl][tx];
        float diff = q - in;
        if (en) outq[(((size_t)b * 256 + ct * 32 + cl) << 10) + ht * 32 + tx] = in + diff;
        local = fmaf(diff, diff, local);
    }
    __shared__ float red[256];
    red[threadIdx.x] = local;
    __syncthreads();
    for (int sfr = 128; sfr; sfr >>= 1) {
        if (threadIdx.x < sfr) red[threadIdx.x] += red[threadIdx.x + sfr];
        __syncthreads();
    }
    if (threadIdx.x == 0) g_partial[bid] = red[0];
}

__global__ void k_loss(float* __restrict__ out_loss) {
    __shared__ float red[256];
    float s = 0.0f;
    int base = threadIdx.x * 32;
#pragma unroll
    for (int i = 0; i < 32; i++) s += g_partial[base + i];
    red[threadIdx.x] = s;
    __syncthreads();
    for (int t = 128; t; t >>= 1) {
        if (threadIdx.x < t) red[threadIdx.x] += red[threadIdx.x + t];
        __syncthreads();
    }
    if (threadIdx.x == 0) {
        float m = red[0] / 8388608.0f;
        out_loss[0] = m + 0.25f * m;
    }
}

__global__ void k_onehot(float* __restrict__ enc, float* __restrict__ outi,
                         int ee, int ei) {
    int n = blockIdx.x * 256 + threadIdx.x;
    int idx = g_idx[n];
    if (ee) enc[(long long)n * 1024 + idx] = 1.0f;
    if (ei) outi[n] = (float)idx;
}

// ===========================================================================
extern "C" void kernel_launch(void* const* d_in, const int* in_sizes, int n_in,
                              void* d_out, int out_size) {
    const float* x  = (const float*)d_in[0];
    const float* cb = (const float*)d_in[1];
    if (n_in >= 2 && in_sizes[0] == KCODES * DDIM && in_sizes[1] == (int)Q_ELEMS) {
        const float* t = x; x = cb; cb = t;
    }
    float* out = (float*)d_out;

    long long os = (long long)out_size;
    long long off_loss = -1, off_q = -1, off_e = -1, off_i = -1;
    if (os == 1 + Q_ELEMS + E_ELEMS + I_ELEMS) {
        off_loss = 0; off_q = 1; off_e = 1 + Q_ELEMS; off_i = 1 + Q_ELEMS + E_ELEMS;
    } else if (os == Q_ELEMS) {
        off_q = 0;
    } else if (os == 1) {
        off_loss = 0;
    } else if (os == 1 + Q_ELEMS) {
        off_loss = 0; off_q = 1;
    } else {
        if (os >= 1) off_loss = 0;
        if (os >= 1 + Q_ELEMS) off_q = 1;
        if (os >= 1 + Q_ELEMS + E_ELEMS) off_e = 1 + Q_ELEMS;
        if (os >= 1 + Q_ELEMS + E_ELEMS + I_ELEMS) off_i = 1 + Q_ELEMS + E_ELEMS;
    }

    cudaFuncSetAttribute(k_dist_mma, cudaFuncAttributeMaxDynamicSharedMemorySize, DIST_SMEM);

    k_ee<<<128, 256>>>(cb);
    k_xx<<<128, 256>>>(x);
    k_splite<<<1024, 256>>>(cb);
    k_splitx<<<8192, 256>>>(x);
    k_dist_mma<<<256, 256, DIST_SMEM>>>();
    k_refine<<<4096, 256>>>(cb);

    k_quant2<<<8192, 256>>>(x, cb,
                            (off_q >= 0) ? (out + off_q) : out,
                            (off_q >= 0) ? 1 : 0);
    if (off_loss >= 0) k_loss<<<1, 256>>>(out + off_loss);

    if (off_e >= 0)
        cudaMemsetAsync(out + off_e, 0, (size_t)E_ELEMS * sizeof(float));
    k_onehot<<<128, 256>>>((off_e >= 0) ? (out + off_e) : out,
                           (off_i >= 0) ? (out + off_i) : out,
                           (off_e >= 0) ? 1 : 0,
                           (off_i >= 0) ? 1 : 0);
}

// round 5
// speedup vs baseline: 2.1382x; 1.8220x over previous
#include <cuda_runtime.h>
#include <cuda_bf16.h>
#include <stdint.h>

#define N_ROWS 32768
#define KCODES 1024
#define DDIM   256

#define Q_ELEMS 8388608LL      // 32*256*32*32
#define E_ELEMS 33554432LL     // 32768*1024
#define I_ELEMS 32768LL

__device__ float g_ee[KCODES];
__device__ float g_xx[N_ROWS];
__device__ int   g_idx[N_ROWS];
__device__ float g_partial[8192];
__device__ __align__(16) __nv_bfloat16 g_X1[N_ROWS * DDIM];
__device__ __align__(16) __nv_bfloat16 g_E1[KCODES * DDIM];
__device__ __align__(16) float g_XT[N_ROWS * DDIM];          // exact fp32, row-major
__device__ __align__(16) float g_D[(size_t)N_ROWS * KCODES]; // approx distances

// ======================= baseline-PTX helpers ==============================
__device__ __forceinline__ uint32_t smem_u32(const void* p) {
    uint32_t a;
    asm("{ .reg .u64 t; cvta.to.shared.u64 t, %1; cvt.u32.u64 %0, t; }" : "=r"(a) : "l"(p));
    return a;
}
#define CP16(dst, src) \
    asm volatile("cp.async.cg.shared.global [%0], [%1], 16;" :: "r"(dst), "l"(src))
#define CP_COMMIT() asm volatile("cp.async.commit_group;" ::: "memory")

#define LDSM4(r, a) \
    asm volatile("ldmatrix.sync.aligned.m8n8.x4.shared.b16 {%0,%1,%2,%3}, [%4];" \
        : "=r"((r)[0]), "=r"((r)[1]), "=r"((r)[2]), "=r"((r)[3]) : "r"(a))

#define MMA16816(d, a, b0v, b1v) \
    asm volatile("mma.sync.aligned.m16n8k16.row.col.f32.bf16.bf16.f32 " \
        "{%0,%1,%2,%3}, {%4,%5,%6,%7}, {%8,%9}, {%0,%1,%2,%3};" \
        : "+f"((d)[0]), "+f"((d)[1]), "+f"((d)[2]), "+f"((d)[3]) \
        : "r"((a)[0]), "r"((a)[1]), "r"((a)[2]), "r"((a)[3]), "r"(b0v), "r"(b1v))

// ======================= precompute kernels ================================
__global__ void k_ee(const float* __restrict__ cb) {
    int code = blockIdx.x * 8 + (threadIdx.x >> 5);
    int lane = threadIdx.x & 31;
    const float* row = cb + code * DDIM;
    double s = 0.0;
#pragma unroll
    for (int i = 0; i < 8; i++) { float v = row[lane + i * 32]; s += (double)v * v; }
#pragma unroll
    for (int m = 16; m; m >>= 1) s += __shfl_xor_sync(0xffffffffu, s, m);
    if (lane == 0) g_ee[code] = (float)s;
}

__global__ void k_xx(const float* __restrict__ x) {
    int n = blockIdx.x * 256 + threadIdx.x;
    int b = n >> 10, hw = n & 1023;
    const float* base = x + (size_t)b * 262144 + hw;
    double s = 0.0;
#pragma unroll 4
    for (int c = 0; c < 256; c++) { float v = base[(size_t)c * 1024]; s += (double)v * v; }
    g_xx[n] = (float)s;
}

// transpose + fp32 copy + bf16 hi of x: [B,C,H,W] -> [n][d]
__global__ void k_splitx(const float* __restrict__ x) {
    __shared__ float s[32][33];
    int bid = blockIdx.x;
    int b = bid >> 8, ct = (bid >> 5) & 7, ht = bid & 31;
    int tx = threadIdx.x & 31, ty = threadIdx.x >> 5;
#pragma unroll
    for (int r = 0; r < 4; r++)
        s[ty + r * 8][tx] = x[(((size_t)b * 256 + ct * 32 + ty + r * 8) << 10) + ht * 32 + tx];
    __syncthreads();
#pragma unroll
    for (int r = 0; r < 4; r++) {
        int hwl = ty + r * 8;
        int n = (b << 10) + ht * 32 + hwl;
        float v = s[tx][hwl];
        g_XT[(size_t)n * 256 + ct * 32 + tx] = v;
        g_X1[(size_t)n * 256 + ct * 32 + tx] = __float2bfloat16(v);
    }
}

__global__ void k_splite(const float* __restrict__ cb) {
    int i = blockIdx.x * 256 + threadIdx.x;
    g_E1[i] = __float2bfloat16(cb[i]);
}

// ======================= HMMA distance GEMM ================================
// A resident: 128 rows x 512B, pitch 528  -> [0, 67584)
// B stages:   3 x (128 rows x 128B, pitch 144 = 18432) -> [67584, 122880)
// es[1024] @122880, xs[128] @126976; total 127488
#define A_PITCH 528
#define SM_B    67584
#define B_PITCH 144
#define BSTG    18432
#define SM_ES   122880
#define SM_XS   126976
#define DIST_SMEM 127488

__device__ __forceinline__ void issue_b(uint32_t smem0, int stg, int t, int tid) {
    int nb = t >> 2, kc = t & 3;
    uint32_t dstb = smem0 + SM_B + stg * BSTG;
#pragma unroll
    for (int i = 0; i < 4; i++) {
        int idx = tid + i * 256;
        int r = idx >> 3, g = idx & 7;
        CP16(dstb + r * B_PITCH + g * 16,
             g_E1 + (size_t)(nb * 128 + r) * 256 + kc * 64 + g * 8);
    }
    CP_COMMIT();
}

__global__ void __launch_bounds__(256, 1) k_dist_mma() {
    extern __shared__ char smem[];
    float* es = (float*)(smem + SM_ES);
    float* xs = (float*)(smem + SM_XS);

    int tid = threadIdx.x, lane = tid & 31, wid = tid >> 5;
    int warp_m = wid & 1, warp_n = wid >> 1;
    int n0 = blockIdx.x * 128;
    uint32_t smem0 = smem_u32(smem);

    // A resident (cp.async group 0): 128 rows x 512B
#pragma unroll
    for (int i = 0; i < 16; i++) {
        int idx = tid + i * 256;
        int r = idx >> 5, g = idx & 31;
        CP16(smem0 + r * A_PITCH + g * 16, g_X1 + (size_t)(n0 + r) * 256 + g * 8);
    }
    CP_COMMIT();
    issue_b(smem0, 0, 0, tid);
    issue_b(smem0, 1, 1, tid);

    for (int i = tid; i < KCODES; i += 256) es[i] = g_ee[i];
    if (tid < 128) xs[tid] = g_xx[n0 + tid];

    uint32_t a_base = smem0 + (warp_m * 64 + (lane & 15)) * A_PITCH + (lane >> 4) * 16;
    uint32_t b_base = smem0 + SM_B + (warp_n * 32 + (lane & 7)) * B_PITCH + (lane >> 3) * 16;

    int gq = lane >> 2, iq = lane & 3;

    for (int nb = 0; nb < 8; nb++) {
        float acc[4][4][4];
#pragma unroll
        for (int mt = 0; mt < 4; mt++)
#pragma unroll
            for (int nt = 0; nt < 4; nt++)
#pragma unroll
                for (int q = 0; q < 4; q++) acc[mt][nt][q] = 0.0f;

        for (int kc = 0; kc < 4; kc++) {
            int t = nb * 4 + kc;
            if (t + 2 < 32) issue_b(smem0, (t + 2) % 3, t + 2, tid);
            if (t < 30)      asm volatile("cp.async.wait_group 2;" ::: "memory");
            else if (t == 30) asm volatile("cp.async.wait_group 1;" ::: "memory");
            else              asm volatile("cp.async.wait_group 0;" ::: "memory");
            __syncthreads();

            uint32_t bst = b_base + (t % 3) * BSTG;
            uint32_t ab = a_base + kc * 128;
#pragma unroll
            for (int kh = 0; kh < 2; kh++) {
                uint32_t bfr[4][4];
#pragma unroll
                for (int nt = 0; nt < 4; nt++)
                    LDSM4(bfr[nt], bst + nt * (8 * B_PITCH) + kh * 64);
#pragma unroll
                for (int ks = 0; ks < 2; ks++) {
                    uint32_t afr[4][4];
#pragma unroll
                    for (int mt = 0; mt < 4; mt++)
                        LDSM4(afr[mt], ab + mt * (16 * A_PITCH) + kh * 64 + ks * 32);
#pragma unroll
                    for (int mt = 0; mt < 4; mt++)
#pragma unroll
                        for (int nt = 0; nt < 4; nt++)
                            MMA16816(acc[mt][nt], afr[mt], bfr[nt][ks * 2], bfr[nt][ks * 2 + 1]);
                }
            }
            __syncthreads();
        }

        // epilogue: store approximate snapped distances for this code tile
#pragma unroll
        for (int mt = 0; mt < 4; mt++) {
#pragma unroll
            for (int h = 0; h < 2; h++) {
                int mrow = warp_m * 64 + mt * 16 + gq + h * 8;
                float xv = xs[mrow];
                size_t base = (size_t)(n0 + mrow) * 1024;
#pragma unroll
                for (int nt = 0; nt < 4; nt++) {
                    int nbase = nb * 128 + warp_n * 32 + nt * 8 + 2 * iq;
                    float d0 = (xv + es[nbase])     - 2.0f * acc[mt][nt][h * 2 + 0];
                    float d1 = (xv + es[nbase + 1]) - 2.0f * acc[mt][nt][h * 2 + 1];
                    *(float2*)(g_D + base + nbase) = make_float2(d0, d1);
                }
            }
        }
    }
}

// ======================= exact rescoring of near-ties ======================
#define TAU 1e-3f
__global__ void __launch_bounds__(256) k_refine(const float* __restrict__ cb) {
    int row = blockIdx.x * 8 + (threadIdx.x >> 5);
    int lane = threadIdx.x & 31;
    const float* Dr = g_D + (size_t)row * 1024;

    float m = 3.4e38f;
#pragma unroll 8
    for (int i = 0; i < 32; i++) m = fminf(m, Dr[lane + 32 * i]);
#pragma unroll
    for (int s = 16; s; s >>= 1) m = fminf(m, __shfl_xor_sync(0xffffffffu, m, s));
    float thr = m + TAU;

    const float4* xr4 = (const float4*)(g_XT + (size_t)row * 256 + lane * 8);
    float4 xa = xr4[0], xb = xr4[1];
    float xx = g_xx[row];

    float best = 3.4e38f;
    int bidx = 0x7fffffff;
    for (int i = 0; i < 32; i++) {
        float d = Dr[lane + 32 * i];
        unsigned ball = __ballot_sync(0xffffffffu, d <= thr);
        while (ball) {
            int src = __ffs(ball) - 1;
            ball &= ball - 1;
            int k = src + 32 * i;
            const float4* cr = (const float4*)(cb + (size_t)k * 256 + lane * 8);
            float4 ca = cr[0], cbv = cr[1];
            float p = xa.x * ca.x;
            p = fmaf(xa.y, ca.y, p);
            p = fmaf(xa.z, ca.z, p);
            p = fmaf(xa.w, ca.w, p);
            p = fmaf(xb.x, cbv.x, p);
            p = fmaf(xb.y, cbv.y, p);
            p = fmaf(xb.z, cbv.z, p);
            p = fmaf(xb.w, cbv.w, p);
#pragma unroll
            for (int s = 16; s; s >>= 1) p += __shfl_xor_sync(0xffffffffu, p, s);
            float dd = (xx + g_ee[k]) - 2.0f * p;
            if (dd < best || (dd == best && k < bidx)) { best = dd; bidx = k; }
        }
    }
    if (lane == 0) g_idx[row] = bidx;
}

// ======================= outputs ==========================================
__global__ void k_quant2(const float* __restrict__ x, const float* __restrict__ cb,
                         float* __restrict__ outq, int en) {
    __shared__ float xs[32][33];
    __shared__ float qs[32][33];
    __shared__ int ids[32];
    int bid = blockIdx.x;
    int b = bid >> 8, ct = (bid >> 5) & 7, ht = bid & 31;
    int tx = threadIdx.x & 31, ty = threadIdx.x >> 5;
    if (threadIdx.x < 32) ids[threadIdx.x] = g_idx[(b << 10) + ht * 32 + threadIdx.x];
#pragma unroll
    for (int r = 0; r < 4; r++)
        xs[ty + r * 8][tx] = x[(((size_t)b * 256 + ct * 32 + ty + r * 8) << 10) + ht * 32 + tx];
    __syncthreads();
#pragma unroll
    for (int r = 0; r < 4; r++) {
        int nl = ty + r * 8;
        qs[tx][nl] = cb[(size_t)ids[nl] * 256 + ct * 32 + tx];
    }
    __syncthreads();
    float local = 0.0f;
#pragma unroll
    for (int r = 0; r < 4; r++) {
        int cl = ty + r * 8;
        float in = xs[cl][tx];
        float q = qs[cl][tx];
        float diff = q - in;
        if (en) outq[(((size_t)b * 256 + ct * 32 + cl) << 10) + ht * 32 + tx] = in + diff;
        local = fmaf(diff, diff, local);
    }
    __shared__ float red[256];
    red[threadIdx.x] = local;
    __syncthreads();
    for (int sfr = 128; sfr; sfr >>= 1) {
        if (threadIdx.x < sfr) red[threadIdx.x] += red[threadIdx.x + sfr];
        __syncthreads();
    }
    if (threadIdx.x == 0) g_partial[bid] = red[0];
}

__global__ void k_loss(float* __restrict__ out_loss) {
    __shared__ float red[256];
    float s = 0.0f;
    int base = threadIdx.x * 32;
#pragma unroll
    for (int i = 0; i < 32; i++) s += g_partial[base + i];
    red[threadIdx.x] = s;
    __syncthreads();
    for (int t = 128; t; t >>= 1) {
        if (threadIdx.x < t) red[threadIdx.x] += red[threadIdx.x + t];
        __syncthreads();
    }
    if (threadIdx.x == 0) {
        float m = red[0] / 8388608.0f;
        out_loss[0] = m + 0.25f * m;
    }
}

__global__ void k_onehot(float* __restrict__ enc, float* __restrict__ outi,
                         int ee, int ei) {
    int n = blockIdx.x * 256 + threadIdx.x;
    int idx = g_idx[n];
    if (ee) enc[(long long)n * 1024 + idx] = 1.0f;
    if (ei) outi[n] = (float)idx;
}

// ===========================================================================
extern "C" void kernel_launch(void* const* d_in, const int* in_sizes, int n_in,
                              void* d_out, int out_size) {
    const float* x  = (const float*)d_in[0];
    const float* cb = (const float*)d_in[1];
    if (n_in >= 2 && in_sizes[0] == KCODES * DDIM && in_sizes[1] == (int)Q_ELEMS) {
        const float* t = x; x = cb; cb = t;
    }
    float* out = (float*)d_out;

    long long os = (long long)out_size;
    long long off_loss = -1, off_q = -1, off_e = -1, off_i = -1;
    if (os == 1 + Q_ELEMS + E_ELEMS + I_ELEMS) {
        off_loss = 0; off_q = 1; off_e = 1 + Q_ELEMS; off_i = 1 + Q_ELEMS + E_ELEMS;
    } else if (os == Q_ELEMS) {
        off_q = 0;
    } else if (os == 1) {
        off_loss = 0;
    } else if (os == 1 + Q_ELEMS) {
        off_loss = 0; off_q = 1;
    } else {
        if (os >= 1) off_loss = 0;
        if (os >= 1 + Q_ELEMS) off_q = 1;
        if (os >= 1 + Q_ELEMS + E_ELEMS) off_e = 1 + Q_ELEMS;
        if (os >= 1 + Q_ELEMS + E_ELEMS + I_ELEMS) off_i = 1 + Q_ELEMS + E_ELEMS;
    }

    cudaFuncSetAttribute(k_dist_mma, cudaFuncAttributeMaxDynamicSharedMemorySize, DIST_SMEM);

    k_ee<<<128, 256>>>(cb);
    k_xx<<<128, 256>>>(x);
    k_splite<<<1024, 256>>>(cb);
    k_splitx<<<8192, 256>>>(x);
    k_dist_mma<<<256, 256, DIST_SMEM>>>();
    k_refine<<<4096, 256>>>(cb);

    k_quant2<<<8192, 256>>>(x, cb,
                            (off_q >= 0) ? (out + off_q) : out,
                            (off_q >= 0) ? 1 : 0);
    if (off_loss >= 0) k_loss<<<1, 256>>>(out + off_loss);

    if (off_e >= 0)
        cudaMemsetAsync(out + off_e, 0, (size_t)E_ELEMS * sizeof(float));
    k_onehot<<<128, 256>>>((off_e >= 0) ? (out + off_e) : out,
                           (off_i >= 0) ? (out + off_i) : out,
                           (off_e >= 0) ? 1 : 0,
                           (off_i >= 0) ? 1 : 0);
}

// round 8
// speedup vs baseline: 2.2485x; 1.0516x over previous
#include <cuda_runtime.h>
#include <cuda_bf16.h>
#include <stdint.h>

#define N_ROWS 32768
#define KCODES 1024
#define DDIM   256

#define Q_ELEMS 8388608LL      // 32*256*32*32
#define E_ELEMS 33554432LL     // 32768*1024
#define I_ELEMS 32768LL

__device__ float g_ee[KCODES];
__device__ float g_xx[N_ROWS];
__device__ int   g_idx[N_ROWS];
__device__ float g_partial[8192];
__device__ __align__(16) __nv_bfloat16 g_X1[N_ROWS * DDIM];
__device__ __align__(16) __nv_bfloat16 g_E1[KCODES * DDIM];
__device__ __align__(16) float g_XT[N_ROWS * DDIM];   // exact fp32 transposed x

// ======================= baseline-PTX helpers ==============================
__device__ __forceinline__ uint32_t smem_u32(const void* p) {
    uint32_t a;
    asm("{ .reg .u64 t; cvta.to.shared.u64 t, %1; cvt.u32.u64 %0, t; }" : "=r"(a) : "l"(p));
    return a;
}
#define CP16(dst, src) \
    asm volatile("cp.async.cg.shared.global [%0], [%1], 16;" :: "r"(dst), "l"(src))
#define CP_COMMIT() asm volatile("cp.async.commit_group;" ::: "memory")

#define LDSM4(r, a) \
    asm volatile("ldmatrix.sync.aligned.m8n8.x4.shared.b16 {%0,%1,%2,%3}, [%4];" \
        : "=r"((r)[0]), "=r"((r)[1]), "=r"((r)[2]), "=r"((r)[3]) : "r"(a))

#define MMA16816(d, a, b0v, b1v) \
    asm volatile("mma.sync.aligned.m16n8k16.row.col.f32.bf16.bf16.f32 " \
        "{%0,%1,%2,%3}, {%4,%5,%6,%7}, {%8,%9}, {%0,%1,%2,%3};" \
        : "+f"((d)[0]), "+f"((d)[1]), "+f"((d)[2]), "+f"((d)[3]) \
        : "r"((a)[0]), "r"((a)[1]), "r"((a)[2]), "r"((a)[3]), "r"(b0v), "r"(b1v))

// ======================= precompute: ee + E1 ===============================
__global__ void k_prep_cb(const float* __restrict__ cb) {
    int code = blockIdx.x * 8 + (threadIdx.x >> 5);
    int lane = threadIdx.x & 31;
    const float* row = cb + code * DDIM;
    double s = 0.0;
#pragma unroll
    for (int i = 0; i < 8; i++) {
        float v = row[lane + i * 32];
        s += (double)v * v;
        g_E1[code * DDIM + lane + i * 32] = __float2bfloat16(v);
    }
#pragma unroll
    for (int m = 16; m; m >>= 1) s += __shfl_xor_sync(0xffffffffu, s, m);
    if (lane == 0) g_ee[code] = (float)s;
}

// ====== transpose + fp32 XT + bf16 X1 + xx, fused. grid 1024, block 256 ====
__global__ void k_splitxx(const float* __restrict__ x) {
    __shared__ float s[256][33];
    int bid = blockIdx.x;
    int b = bid >> 5, hw0 = (bid & 31) * 32;
    int tx = threadIdx.x & 31, ty = threadIdx.x >> 5;
    const float* xb = x + (size_t)b * 262144 + hw0 + tx;
#pragma unroll 8
    for (int g = 0; g < 32; g++) {
        int c = ty + g * 8;
        s[c][tx] = xb[(size_t)c * 1024];
    }
    __syncthreads();
    int wid = ty, lane = tx;
#pragma unroll
    for (int rr = 0; rr < 4; rr++) {
        int r = wid * 4 + rr;
        int n = b * 1024 + hw0 + r;
        double acc = 0.0;
#pragma unroll
        for (int j = 0; j < 8; j++) {
            int d = lane + j * 32;
            float v = s[d][r];
            acc += (double)v * v;
            g_XT[(size_t)n * 256 + d] = v;
            g_X1[(size_t)n * 256 + d] = __float2bfloat16(v);
        }
#pragma unroll
        for (int m = 16; m; m >>= 1) acc += __shfl_xor_sync(0xffffffffu, acc, m);
        if (lane == 0) g_xx[n] = (float)acc;
    }
}

// ======================= HMMA distance GEMM + in-CTA argmin ================
#define A_PITCH 528
#define SM_B    67584
#define B_PITCH 144
#define BSTG    18432
#define SM_ES   122880
#define SM_XS   126976
#define SM_RMIN 127488
#define SM_CCNT 128000
#define SM_CAND 128512
#define MAXCAND 32
#define DIST_SMEM (SM_CAND + 128 * MAXCAND * 4)   // 144896
#define TAU 1e-3f

__device__ __forceinline__ void issue_b(uint32_t smem0, int stg, int t, int tid) {
    int nb = t >> 2, kc = t & 3;
    uint32_t dstb = smem0 + SM_B + stg * BSTG;
#pragma unroll
    for (int i = 0; i < 4; i++) {
        int idx = tid + i * 256;
        int r = idx >> 3, g = idx & 7;
        CP16(dstb + r * B_PITCH + g * 16,
             g_E1 + (size_t)(nb * 128 + r) * 256 + kc * 64 + g * 8);
    }
    CP_COMMIT();
}

__global__ void __launch_bounds__(256, 1) k_dist_mma(const float* __restrict__ cb) {
    extern __shared__ char smem[];
    float* es = (float*)(smem + SM_ES);
    float* xs = (float*)(smem + SM_XS);
    int* rowmin = (int*)(smem + SM_RMIN);
    int* ccnt = (int*)(smem + SM_CCNT);
    int* cand = (int*)(smem + SM_CAND);

    int tid = threadIdx.x, lane = tid & 31, wid = tid >> 5;
    int warp_m = wid & 1, warp_n = wid >> 1;
    int n0 = blockIdx.x * 128;
    uint32_t smem0 = smem_u32(smem);

    // A resident
#pragma unroll
    for (int i = 0; i < 16; i++) {
        int idx = tid + i * 256;
        int r = idx >> 5, g = idx & 31;
        CP16(smem0 + r * A_PITCH + g * 16, g_X1 + (size_t)(n0 + r) * 256 + g * 8);
    }
    CP_COMMIT();
    issue_b(smem0, 0, 0, tid);
    issue_b(smem0, 1, 1, tid);

    for (int i = tid; i < KCODES; i += 256) es[i] = g_ee[i];
    if (tid < 128) {
        xs[tid] = g_xx[n0 + tid];
        rowmin[tid] = 0x7F800000;   // +inf
        ccnt[tid] = 0;
    }

    uint32_t a_base = smem0 + (warp_m * 64 + (lane & 15)) * A_PITCH + (lane >> 4) * 16;
    uint32_t b_base = smem0 + SM_B + (warp_n * 32 + (lane & 7)) * B_PITCH + (lane >> 3) * 16;

    int gq = lane >> 2, iq = lane & 3;

    for (int nb = 0; nb < 8; nb++) {
        float acc[4][4][4];
#pragma unroll
        for (int mt = 0; mt < 4; mt++)
#pragma unroll
            for (int nt = 0; nt < 4; nt++)
#pragma unroll
                for (int q = 0; q < 4; q++) acc[mt][nt][q] = 0.0f;

        for (int kc = 0; kc < 4; kc++) {
            int t = nb * 4 + kc;
            if (t + 2 < 32) issue_b(smem0, (t + 2) % 3, t + 2, tid);
            if (t < 30)       asm volatile("cp.async.wait_group 2;" ::: "memory");
            else if (t == 30) asm volatile("cp.async.wait_group 1;" ::: "memory");
            else              asm volatile("cp.async.wait_group 0;" ::: "memory");
            __syncthreads();

            uint32_t bst = b_base + (t % 3) * BSTG;
            uint32_t ab = a_base + kc * 128;
#pragma unroll
            for (int kh = 0; kh < 2; kh++) {
                uint32_t bfr[4][4];
#pragma unroll
                for (int nt = 0; nt < 4; nt++)
                    LDSM4(bfr[nt], bst + nt * (8 * B_PITCH) + kh * 64);
#pragma unroll
                for (int ks = 0; ks < 2; ks++) {
                    uint32_t afr[4][4];
#pragma unroll
                    for (int mt = 0; mt < 4; mt++)
                        LDSM4(afr[mt], ab + mt * (16 * A_PITCH) + kh * 64 + ks * 32);
#pragma unroll
                    for (int mt = 0; mt < 4; mt++)
#pragma unroll
                        for (int nt = 0; nt < 4; nt++)
                            MMA16816(acc[mt][nt], afr[mt], bfr[nt][ks * 2], bfr[nt][ks * 2 + 1]);
                }
            }
            __syncthreads();
        }

        // ---- epilogue phase 1: update per-row running min ----
#pragma unroll
        for (int mt = 0; mt < 4; mt++) {
#pragma unroll
            for (int h = 0; h < 2; h++) {
                int mrow = warp_m * 64 + mt * 16 + gq + h * 8;
                float xv = xs[mrow];
                float dmin = 3.4e38f;
#pragma unroll
                for (int nt = 0; nt < 4; nt++) {
                    int nbase = nb * 128 + warp_n * 32 + nt * 8 + 2 * iq;
                    float d0 = (xv + es[nbase])     - 2.0f * acc[mt][nt][h * 2 + 0];
                    float d1 = (xv + es[nbase + 1]) - 2.0f * acc[mt][nt][h * 2 + 1];
                    dmin = fminf(dmin, fminf(d0, d1));
                }
                atomicMin(&rowmin[mrow], __float_as_int(dmin));
            }
        }
        __syncthreads();
        // ---- epilogue phase 2: tight capture vs tile-complete running min ----
#pragma unroll
        for (int mt = 0; mt < 4; mt++) {
#pragma unroll
            for (int h = 0; h < 2; h++) {
                int mrow = warp_m * 64 + mt * 16 + gq + h * 8;
                float xv = xs[mrow];
                float thr = __int_as_float(rowmin[mrow]) + TAU;
#pragma unroll
                for (int nt = 0; nt < 4; nt++) {
                    int nbase = nb * 128 + warp_n * 32 + nt * 8 + 2 * iq;
                    float d0 = (xv + es[nbase])     - 2.0f * acc[mt][nt][h * 2 + 0];
                    float d1 = (xv + es[nbase + 1]) - 2.0f * acc[mt][nt][h * 2 + 1];
                    if (d0 <= thr) {
                        int slot = atomicAdd(&ccnt[mrow], 1);
                        if (slot < MAXCAND) cand[mrow * MAXCAND + slot] = nbase;
                    }
                    if (d1 <= thr) {
                        int slot = atomicAdd(&ccnt[mrow], 1);
                        if (slot < MAXCAND) cand[mrow * MAXCAND + slot] = nbase + 1;
                    }
                }
            }
        }
    }
    __syncthreads();

    // exact fp32 rescore of candidates: warp w handles rows w*16..w*16+15
    for (int rr = 0; rr < 16; rr++) {
        int rl = wid * 16 + rr;
        int row = n0 + rl;
        int cnt = ccnt[rl];
        float xx = g_xx[row];
        const float4* xr4 = (const float4*)(g_XT + (size_t)row * 256 + lane * 8);
        float4 xa = xr4[0], xb4 = xr4[1];
        float best = 3.4e38f; int bidx = 0x7fffffff;
        bool overflow = (cnt > MAXCAND);
        int total = overflow ? KCODES : cnt;
        for (int c = 0; c < total; c++) {
            int k = overflow ? c : cand[rl * MAXCAND + c];
            const float4* cr = (const float4*)(cb + (size_t)k * 256 + lane * 8);
            float4 ca = cr[0], cbv = cr[1];
            float p = xa.x * ca.x;
            p = fmaf(xa.y, ca.y, p);
            p = fmaf(xa.z, ca.z, p);
            p = fmaf(xa.w, ca.w, p);
            p = fmaf(xb4.x, cbv.x, p);
            p = fmaf(xb4.y, cbv.y, p);
            p = fmaf(xb4.z, cbv.z, p);
            p = fmaf(xb4.w, cbv.w, p);
#pragma unroll
            for (int m = 16; m; m >>= 1) p += __shfl_xor_sync(0xffffffffu, p, m);
            float dd = (xx + es[k]) - 2.0f * p;
            if (dd < best || (dd == best && k < bidx)) { best = dd; bidx = k; }
        }
        if (lane == 0) g_idx[row] = bidx;
    }
}

// ======================= outputs ==========================================
__global__ void k_quant2(const float* __restrict__ x, const float* __restrict__ cb,
                         float* __restrict__ outq, int en) {
    __shared__ float xs[32][33];
    __shared__ float qs[32][33];
    __shared__ int ids[32];
    int bid = blockIdx.x;
    int b = bid >> 8, ct = (bid >> 5) & 7, ht = bid & 31;
    int tx = threadIdx.x & 31, ty = threadIdx.x >> 5;
    if (threadIdx.x < 32) ids[threadIdx.x] = g_idx[(b << 10) + ht * 32 + threadIdx.x];
#pragma unroll
    for (int r = 0; r < 4; r++)
        xs[ty + r * 8][tx] = x[(((size_t)b * 256 + ct * 32 + ty + r * 8) << 10) + ht * 32 + tx];
    __syncthreads();
#pragma unroll
    for (int r = 0; r < 4; r++) {
        int nl = ty + r * 8;
        qs[tx][nl] = cb[(size_t)ids[nl] * 256 + ct * 32 + tx];
    }
    __syncthreads();
    float local = 0.0f;
#pragma unroll
    for (int r = 0; r < 4; r++) {
        int cl = ty + r * 8;
        float in = xs[cl][tx];
        float q = qs[cl][tx];
        float diff = q - in;
        if (en) outq[(((size_t)b * 256 + ct * 32 + cl) << 10) + ht * 32 + tx] = in + diff;
        local = fmaf(diff, diff, local);
    }
    __shared__ float red[256];
    red[threadIdx.x] = local;
    __syncthreads();
    for (int sfr = 128; sfr; sfr >>= 1) {
        if (threadIdx.x < sfr) red[threadIdx.x] += red[threadIdx.x + sfr];
        __syncthreads();
    }
    if (threadIdx.x == 0) g_partial[bid] = red[0];
}

__global__ void k_loss(float* __restrict__ out_loss) {
    __shared__ float red[256];
    float s = 0.0f;
    int base = threadIdx.x * 32;
#pragma unroll
    for (int i = 0; i < 32; i++) s += g_partial[base + i];
    red[threadIdx.x] = s;
    __syncthreads();
    for (int t = 128; t; t >>= 1) {
        if (threadIdx.x < t) red[threadIdx.x] += red[threadIdx.x + t];
        __syncthreads();
    }
    if (threadIdx.x == 0) {
        float m = red[0] / 8388608.0f;
        out_loss[0] = m + 0.25f * m;
    }
}

// one streaming pass: zeros + one-hot + indices (SCALAR stores — encodings
// slab is only 4-byte aligned inside d_out)
__global__ void k_encodings(float* __restrict__ enc, float* __restrict__ outi,
                            int ee, int ei) {
    int n = blockIdx.x * 8 + (threadIdx.x >> 5);       // row
    int lane = threadIdx.x & 31;
    int idx = g_idx[n];
    if (ee) {
        float* dst = enc + (size_t)n * 1024;
#pragma unroll
        for (int i = 0; i < 32; i++) {
            int j = lane + i * 32;
            dst[j] = (j == idx) ? 1.0f : 0.0f;
        }
    }
    if (ei && lane == 0) outi[n] = (float)idx;
}

// ===========================================================================
extern "C" void kernel_launch(void* const* d_in, const int* in_sizes, int n_in,
                              void* d_out, int out_size) {
    const float* x  = (const float*)d_in[0];
    const float* cb = (const float*)d_in[1];
    if (n_in >= 2 && in_sizes[0] == KCODES * DDIM && in_sizes[1] == (int)Q_ELEMS) {
        const float* t = x; x = cb; cb = t;
    }
    float* out = (float*)d_out;

    long long os = (long long)out_size;
    long long off_loss = -1, off_q = -1, off_e = -1, off_i = -1;
    if (os == 1 + Q_ELEMS + E_ELEMS + I_ELEMS) {
        off_loss = 0; off_q = 1; off_e = 1 + Q_ELEMS; off_i = 1 + Q_ELEMS + E_ELEMS;
    } else if (os == Q_ELEMS) {
        off_q = 0;
    } else if (os == 1) {
        off_loss = 0;
    } else if (os == 1 + Q_ELEMS) {
        off_loss = 0; off_q = 1;
    } else {
        if (os >= 1) off_loss = 0;
        if (os >= 1 + Q_ELEMS) off_q = 1;
        if (os >= 1 + Q_ELEMS + E_ELEMS) off_e = 1 + Q_ELEMS;
        if (os >= 1 + Q_ELEMS + E_ELEMS + I_ELEMS) off_i = 1 + Q_ELEMS + E_ELEMS;
    }

    cudaFuncSetAttribute(k_dist_mma, cudaFuncAttributeMaxDynamicSharedMemorySize, DIST_SMEM);

    k_prep_cb<<<128, 256>>>(cb);
    k_splitxx<<<1024, 256>>>(x);
    k_dist_mma<<<256, 256, DIST_SMEM>>>(cb);

    k_quant2<<<8192, 256>>>(x, cb,
                            (off_q >= 0) ? (out + off_q) : out,
                            (off_q >= 0) ? 1 : 0);
    if (off_loss >= 0) k_loss<<<1, 256>>>(out + off_loss);

    k_encodings<<<4096, 256>>>((off_e >= 0) ? (out + off_e) : out,
                               (off_i >= 0) ? (out + off_i) : out,
                               (off_e >= 0) ? 1 : 0,
                               (off_i >= 0) ? 1 : 0);
}

// round 9
// speedup vs baseline: 2.4975x; 1.1108x over previous
#include <cuda_runtime.h>
#include <cuda_bf16.h>
#include <stdint.h>

#define N_ROWS 32768
#define KCODES 1024
#define DDIM   256

#define Q_ELEMS 8388608LL      // 32*256*32*32
#define E_ELEMS 33554432LL     // 32768*1024
#define I_ELEMS 32768LL

__device__ float g_ee[KCODES];
__device__ float g_xx[N_ROWS];
__device__ int   g_idx[N_ROWS];
__device__ float g_partial[8192];
__device__ __align__(16) __nv_bfloat16 g_X1[N_ROWS * DDIM];
__device__ __align__(16) __nv_bfloat16 g_E1[KCODES * DDIM];
__device__ __align__(16) float g_XT[N_ROWS * DDIM];   // exact fp32 transposed x

// ======================= baseline-PTX helpers ==============================
__device__ __forceinline__ uint32_t smem_u32(const void* p) {
    uint32_t a;
    asm("{ .reg .u64 t; cvta.to.shared.u64 t, %1; cvt.u32.u64 %0, t; }" : "=r"(a) : "l"(p));
    return a;
}
#define CP16(dst, src) \
    asm volatile("cp.async.cg.shared.global [%0], [%1], 16;" :: "r"(dst), "l"(src))
#define CP_COMMIT() asm volatile("cp.async.commit_group;" ::: "memory")

#define LDSM4(r, a) \
    asm volatile("ldmatrix.sync.aligned.m8n8.x4.shared.b16 {%0,%1,%2,%3}, [%4];" \
        : "=r"((r)[0]), "=r"((r)[1]), "=r"((r)[2]), "=r"((r)[3]) : "r"(a))

#define MMA16816(d, a, b0v, b1v) \
    asm volatile("mma.sync.aligned.m16n8k16.row.col.f32.bf16.bf16.f32 " \
        "{%0,%1,%2,%3}, {%4,%5,%6,%7}, {%8,%9}, {%0,%1,%2,%3};" \
        : "+f"((d)[0]), "+f"((d)[1]), "+f"((d)[2]), "+f"((d)[3]) \
        : "r"((a)[0]), "r"((a)[1]), "r"((a)[2]), "r"((a)[3]), "r"(b0v), "r"(b1v))

// ======================= precompute: ee + E1 ===============================
__global__ void k_prep_cb(const float* __restrict__ cb) {
    int code = blockIdx.x * 8 + (threadIdx.x >> 5);
    int lane = threadIdx.x & 31;
    const float* row = cb + code * DDIM;
    double s = 0.0;
#pragma unroll
    for (int i = 0; i < 8; i++) {
        float v = row[lane + i * 32];
        s += (double)v * v;
        g_E1[code * DDIM + lane + i * 32] = __float2bfloat16(v);
    }
#pragma unroll
    for (int m = 16; m; m >>= 1) s += __shfl_xor_sync(0xffffffffu, s, m);
    if (lane == 0) g_ee[code] = (float)s;
}

// ====== transpose + fp32 XT + bf16 X1 + xx, fused. grid 1024, block 256 ====
__global__ void k_splitxx(const float* __restrict__ x) {
    __shared__ float s[256][33];
    int bid = blockIdx.x;
    int b = bid >> 5, hw0 = (bid & 31) * 32;
    int tx = threadIdx.x & 31, ty = threadIdx.x >> 5;
    const float* xb = x + (size_t)b * 262144 + hw0 + tx;
#pragma unroll 8
    for (int g = 0; g < 32; g++) {
        int c = ty + g * 8;
        s[c][tx] = xb[(size_t)c * 1024];
    }
    __syncthreads();
    int wid = ty, lane = tx;
#pragma unroll
    for (int rr = 0; rr < 4; rr++) {
        int r = wid * 4 + rr;
        int n = b * 1024 + hw0 + r;
        double acc = 0.0;
#pragma unroll
        for (int j = 0; j < 8; j++) {
            int d = lane + j * 32;
            float v = s[d][r];
            acc += (double)v * v;
            g_XT[(size_t)n * 256 + d] = v;
            g_X1[(size_t)n * 256 + d] = __float2bfloat16(v);
        }
#pragma unroll
        for (int m = 16; m; m >>= 1) acc += __shfl_xor_sync(0xffffffffu, acc, m);
        if (lane == 0) g_xx[n] = (float)acc;
    }
}

// ======================= HMMA distance GEMM + in-CTA argmin ================
// 512 threads / 16 warps: warp_m = wid&3 (32 rows), warp_n = wid>>2 (32 cols)
#define A_PITCH 528
#define SM_B    67584
#define B_PITCH 144
#define BSTG    18432
#define SM_ES   122880
#define SM_XS   126976
#define SM_RMIN 127488
#define SM_CCNT 128000
#define SM_CAND 128512
#define MAXCAND 32
#define DIST_SMEM (SM_CAND + 128 * MAXCAND * 4)   // 144896
#define TAU 1e-3f

__device__ __forceinline__ void issue_b(uint32_t smem0, int stg, int t, int tid) {
    int nb = t >> 2, kc = t & 3;
    uint32_t dstb = smem0 + SM_B + stg * BSTG;
#pragma unroll
    for (int i = 0; i < 2; i++) {
        int idx = tid + i * 512;
        int r = idx >> 3, g = idx & 7;
        CP16(dstb + r * B_PITCH + g * 16,
             g_E1 + (size_t)(nb * 128 + r) * 256 + kc * 64 + g * 8);
    }
    CP_COMMIT();
}

__global__ void __launch_bounds__(512, 1) k_dist_mma(const float* __restrict__ cb) {
    extern __shared__ char smem[];
    float* es = (float*)(smem + SM_ES);
    float* xs = (float*)(smem + SM_XS);
    int* rowmin = (int*)(smem + SM_RMIN);
    int* ccnt = (int*)(smem + SM_CCNT);
    int* cand = (int*)(smem + SM_CAND);

    int tid = threadIdx.x, lane = tid & 31, wid = tid >> 5;
    int warp_m = wid & 3, warp_n = wid >> 2;
    int n0 = blockIdx.x * 128;
    uint32_t smem0 = smem_u32(smem);

    // A resident: 128 rows x 512B
#pragma unroll
    for (int i = 0; i < 8; i++) {
        int idx = tid + i * 512;
        int r = idx >> 5, g = idx & 31;
        CP16(smem0 + r * A_PITCH + g * 16, g_X1 + (size_t)(n0 + r) * 256 + g * 8);
    }
    CP_COMMIT();
    issue_b(smem0, 0, 0, tid);
    issue_b(smem0, 1, 1, tid);

    for (int i = tid; i < KCODES; i += 512) es[i] = g_ee[i];
    if (tid < 128) {
        xs[tid] = g_xx[n0 + tid];
        rowmin[tid] = 0x7F800000;   // +inf
        ccnt[tid] = 0;
    }

    uint32_t a_base = smem0 + (warp_m * 32 + (lane & 15)) * A_PITCH + (lane >> 4) * 16;
    uint32_t b_base = smem0 + SM_B + (warp_n * 32 + (lane & 7)) * B_PITCH + (lane >> 3) * 16;

    int gq = lane >> 2, iq = lane & 3;

    for (int nb = 0; nb < 8; nb++) {
        float acc[2][4][4];
#pragma unroll
        for (int mt = 0; mt < 2; mt++)
#pragma unroll
            for (int nt = 0; nt < 4; nt++)
#pragma unroll
                for (int q = 0; q < 4; q++) acc[mt][nt][q] = 0.0f;

        for (int kc = 0; kc < 4; kc++) {
            int t = nb * 4 + kc;
            if (t + 2 < 32) issue_b(smem0, (t + 2) % 3, t + 2, tid);
            if (t < 30)       asm volatile("cp.async.wait_group 2;" ::: "memory");
            else if (t == 30) asm volatile("cp.async.wait_group 1;" ::: "memory");
            else              asm volatile("cp.async.wait_group 0;" ::: "memory");
            __syncthreads();

            uint32_t bst = b_base + (t % 3) * BSTG;
            uint32_t ab = a_base + kc * 128;
#pragma unroll
            for (int kh = 0; kh < 2; kh++) {
                uint32_t bfr[4][4];
#pragma unroll
                for (int nt = 0; nt < 4; nt++)
                    LDSM4(bfr[nt], bst + nt * (8 * B_PITCH) + kh * 64);
#pragma unroll
                for (int ks = 0; ks < 2; ks++) {
                    uint32_t afr[2][4];
#pragma unroll
                    for (int mt = 0; mt < 2; mt++)
                        LDSM4(afr[mt], ab + mt * (16 * A_PITCH) + kh * 64 + ks * 32);
#pragma unroll
                    for (int mt = 0; mt < 2; mt++)
#pragma unroll
                        for (int nt = 0; nt < 4; nt++)
                            MMA16816(acc[mt][nt], afr[mt], bfr[nt][ks * 2], bfr[nt][ks * 2 + 1]);
                }
            }
            __syncthreads();
        }

        // ---- epilogue phase 1: per-row running min ----
#pragma unroll
        for (int mt = 0; mt < 2; mt++) {
#pragma unroll
            for (int h = 0; h < 2; h++) {
                int mrow = warp_m * 32 + mt * 16 + gq + h * 8;
                float xv = xs[mrow];
                float dmin = 3.4e38f;
#pragma unroll
                for (int nt = 0; nt < 4; nt++) {
                    int nbase = nb * 128 + warp_n * 32 + nt * 8 + 2 * iq;
                    float d0 = (xv + es[nbase])     - 2.0f * acc[mt][nt][h * 2 + 0];
                    float d1 = (xv + es[nbase + 1]) - 2.0f * acc[mt][nt][h * 2 + 1];
                    dmin = fminf(dmin, fminf(d0, d1));
                }
                atomicMin(&rowmin[mrow], __float_as_int(dmin));
            }
        }
        __syncthreads();
        // ---- epilogue phase 2: tight capture ----
#pragma unroll
        for (int mt = 0; mt < 2; mt++) {
#pragma unroll
            for (int h = 0; h < 2; h++) {
                int mrow = warp_m * 32 + mt * 16 + gq + h * 8;
                float xv = xs[mrow];
                float thr = __int_as_float(rowmin[mrow]) + TAU;
#pragma unroll
                for (int nt = 0; nt < 4; nt++) {
                    int nbase = nb * 128 + warp_n * 32 + nt * 8 + 2 * iq;
                    float d0 = (xv + es[nbase])     - 2.0f * acc[mt][nt][h * 2 + 0];
                    float d1 = (xv + es[nbase + 1]) - 2.0f * acc[mt][nt][h * 2 + 1];
                    if (d0 <= thr) {
                        int slot = atomicAdd(&ccnt[mrow], 1);
                        if (slot < MAXCAND) cand[mrow * MAXCAND + slot] = nbase;
                    }
                    if (d1 <= thr) {
                        int slot = atomicAdd(&ccnt[mrow], 1);
                        if (slot < MAXCAND) cand[mrow * MAXCAND + slot] = nbase + 1;
                    }
                }
            }
        }
    }
    __syncthreads();

    // exact fp32 rescore: warp w handles rows w*8..w*8+7
    for (int rr = 0; rr < 8; rr++) {
        int rl = wid * 8 + rr;
        int row = n0 + rl;
        int cnt = ccnt[rl];
        float xx = g_xx[row];
        const float4* xr4 = (const float4*)(g_XT + (size_t)row * 256 + lane * 8);
        float4 xa = xr4[0], xb4 = xr4[1];
        float best = 3.4e38f; int bidx = 0x7fffffff;
        bool overflow = (cnt > MAXCAND);
        int total = overflow ? KCODES : cnt;
        for (int c = 0; c < total; c++) {
            int k = overflow ? c : cand[rl * MAXCAND + c];
            const float4* cr = (const float4*)(cb + (size_t)k * 256 + lane * 8);
            float4 ca = cr[0], cbv = cr[1];
            float p = xa.x * ca.x;
            p = fmaf(xa.y, ca.y, p);
            p = fmaf(xa.z, ca.z, p);
            p = fmaf(xa.w, ca.w, p);
            p = fmaf(xb4.x, cbv.x, p);
            p = fmaf(xb4.y, cbv.y, p);
            p = fmaf(xb4.z, cbv.z, p);
            p = fmaf(xb4.w, cbv.w, p);
#pragma unroll
            for (int m = 16; m; m >>= 1) p += __shfl_xor_sync(0xffffffffu, p, m);
            float dd = (xx + es[k]) - 2.0f * p;
            if (dd < best || (dd == best && k < bidx)) { best = dd; bidx = k; }
        }
        if (lane == 0) g_idx[row] = bidx;
    }
}

// ======================= outputs ==========================================
__global__ void k_quant2(const float* __restrict__ x, const float* __restrict__ cb,
                         float* __restrict__ outq, int en) {
    __shared__ float xs[32][33];
    __shared__ float qs[32][33];
    __shared__ int ids[32];
    int bid = blockIdx.x;
    int b = bid >> 8, ct = (bid >> 5) & 7, ht = bid & 31;
    int tx = threadIdx.x & 31, ty = threadIdx.x >> 5;
    if (threadIdx.x < 32) ids[threadIdx.x] = g_idx[(b << 10) + ht * 32 + threadIdx.x];
#pragma unroll
    for (int r = 0; r < 4; r++)
        xs[ty + r * 8][tx] = x[(((size_t)b * 256 + ct * 32 + ty + r * 8) << 10) + ht * 32 + tx];
    __syncthreads();
#pragma unroll
    for (int r = 0; r < 4; r++) {
        int nl = ty + r * 8;
        qs[tx][nl] = cb[(size_t)ids[nl] * 256 + ct * 32 + tx];
    }
    __syncthreads();
    float local = 0.0f;
#pragma unroll
    for (int r = 0; r < 4; r++) {
        int cl = ty + r * 8;
        float in = xs[cl][tx];
        float q = qs[cl][tx];
        float diff = q - in;
        if (en) outq[(((size_t)b * 256 + ct * 32 + cl) << 10) + ht * 32 + tx] = in + diff;
        local = fmaf(diff, diff, local);
    }
    __shared__ float red[256];
    red[threadIdx.x] = local;
    __syncthreads();
    for (int sfr = 128; sfr; sfr >>= 1) {
        if (threadIdx.x < sfr) red[threadIdx.x] += red[threadIdx.x + sfr];
        __syncthreads();
    }
    if (threadIdx.x == 0) g_partial[bid] = red[0];
}

__global__ void k_loss(float* __restrict__ out_loss) {
    __shared__ float red[256];
    float s = 0.0f;
    int base = threadIdx.x * 32;
#pragma unroll
    for (int i = 0; i < 32; i++) s += g_partial[base + i];
    red[threadIdx.x] = s;
    __syncthreads();
    for (int t = 128; t; t >>= 1) {
        if (threadIdx.x < t) red[threadIdx.x] += red[threadIdx.x + t];
        __syncthreads();
    }
    if (threadIdx.x == 0) {
        float m = red[0] / 8388608.0f;
        out_loss[0] = m + 0.25f * m;
    }
}

// streaming zeros + one-hot + indices (SCALAR stores — slab 4B-aligned only)
__global__ void k_encodings(float* __restrict__ enc, float* __restrict__ outi,
                            int ee, int ei) {
    int n = blockIdx.x * 8 + (threadIdx.x >> 5);
    int lane = threadIdx.x & 31;
    int idx = g_idx[n];
    if (ee) {
        float* dst = enc + (size_t)n * 1024;
#pragma unroll
        for (int i = 0; i < 32; i++) {
            int j = lane + i * 32;
            dst[j] = (j == idx) ? 1.0f : 0.0f;
        }
    }
    if (ei && lane == 0) outi[n] = (float)idx;
}

// ===========================================================================
extern "C" void kernel_launch(void* const* d_in, const int* in_sizes, int n_in,
                              void* d_out, int out_size) {
    const float* x  = (const float*)d_in[0];
    const float* cb = (const float*)d_in[1];
    if (n_in >= 2 && in_sizes[0] == KCODES * DDIM && in_sizes[1] == (int)Q_ELEMS) {
        const float* t = x; x = cb; cb = t;
    }
    float* out = (float*)d_out;

    long long os = (long long)out_size;
    long long off_loss = -1, off_q = -1, off_e = -1, off_i = -1;
    if (os == 1 + Q_ELEMS + E_ELEMS + I_ELEMS) {
        off_loss = 0; off_q = 1; off_e = 1 + Q_ELEMS; off_i = 1 + Q_ELEMS + E_ELEMS;
    } else if (os == Q_ELEMS) {
        off_q = 0;
    } else if (os == 1) {
        off_loss = 0;
    } else if (os == 1 + Q_ELEMS) {
        off_loss = 0; off_q = 1;
    } else {
        if (os >= 1) off_loss = 0;
        if (os >= 1 + Q_ELEMS) off_q = 1;
        if (os >= 1 + Q_ELEMS + E_ELEMS) off_e = 1 + Q_ELEMS;
        if (os >= 1 + Q_ELEMS + E_ELEMS + I_ELEMS) off_i = 1 + Q_ELEMS + E_ELEMS;
    }

    cudaFuncSetAttribute(k_dist_mma, cudaFuncAttributeMaxDynamicSharedMemorySize, DIST_SMEM);

    k_prep_cb<<<128, 256>>>(cb);
    k_splitxx<<<1024, 256>>>(x);
    k_dist_mma<<<256, 512, DIST_SMEM>>>(cb);

    k_quant2<<<8192, 256>>>(x, cb,
                            (off_q >= 0) ? (out + off_q) : out,
                            (off_q >= 0) ? 1 : 0);
    if (off_loss >= 0) k_loss<<<1, 256>>>(out + off_loss);

    k_encodings<<<4096, 256>>>((off_e >= 0) ? (out + off_e) : out,
                               (off_i >= 0) ? (out + off_i) : out,
                               (off_e >= 0) ? 1 : 0,
                               (off_i >= 0) ? 1 : 0);
}

// round 10
// speedup vs baseline: 2.5375x; 1.0160x over previous
#include <cuda_runtime.h>
#include <cuda_bf16.h>
#include <stdint.h>

#define N_ROWS 32768
#define KCODES 1024
#define DDIM   256

#define Q_ELEMS 8388608LL      // 32*256*32*32
#define E_ELEMS 33554432LL     // 32768*1024
#define I_ELEMS 32768LL

__device__ float g_ee[KCODES];
__device__ float g_xx[N_ROWS];
__device__ int   g_idx[N_ROWS];
__device__ float g_partial[8192];
__device__ __align__(16) __nv_bfloat16 g_X1[N_ROWS * DDIM];
__device__ __align__(16) __nv_bfloat16 g_E1[KCODES * DDIM];
__device__ __align__(16) float g_XT[N_ROWS * DDIM];   // exact fp32 transposed x

// ======================= baseline-PTX helpers ==============================
__device__ __forceinline__ uint32_t smem_u32(const void* p) {
    uint32_t a;
    asm("{ .reg .u64 t; cvta.to.shared.u64 t, %1; cvt.u32.u64 %0, t; }" : "=r"(a) : "l"(p));
    return a;
}
#define CP16(dst, src) \
    asm volatile("cp.async.cg.shared.global [%0], [%1], 16;" :: "r"(dst), "l"(src))
#define CP_COMMIT() asm volatile("cp.async.commit_group;" ::: "memory")

#define LDSM4(r, a) \
    asm volatile("ldmatrix.sync.aligned.m8n8.x4.shared.b16 {%0,%1,%2,%3}, [%4];" \
        : "=r"((r)[0]), "=r"((r)[1]), "=r"((r)[2]), "=r"((r)[3]) : "r"(a))

#define MMA16816(d, a, b0v, b1v) \
    asm volatile("mma.sync.aligned.m16n8k16.row.col.f32.bf16.bf16.f32 " \
        "{%0,%1,%2,%3}, {%4,%5,%6,%7}, {%8,%9}, {%0,%1,%2,%3};" \
        : "+f"((d)[0]), "+f"((d)[1]), "+f"((d)[2]), "+f"((d)[3]) \
        : "r"((a)[0]), "r"((a)[1]), "r"((a)[2]), "r"((a)[3]), "r"(b0v), "r"(b1v))

// ======================= precompute: ee + E1 ===============================
__global__ void k_prep_cb(const float* __restrict__ cb) {
    int code = blockIdx.x * 8 + (threadIdx.x >> 5);
    int lane = threadIdx.x & 31;
    const float* row = cb + code * DDIM;
    double s = 0.0;
#pragma unroll
    for (int i = 0; i < 8; i++) {
        float v = row[lane + i * 32];
        s += (double)v * v;
        g_E1[code * DDIM + lane + i * 32] = __float2bfloat16(v);
    }
#pragma unroll
    for (int m = 16; m; m >>= 1) s += __shfl_xor_sync(0xffffffffu, s, m);
    if (lane == 0) g_ee[code] = (float)s;
}

// ====== transpose + fp32 XT + bf16 X1 + xx, fused. grid 1024, block 256 ====
__global__ void k_splitxx(const float* __restrict__ x) {
    __shared__ float s[256][33];
    int bid = blockIdx.x;
    int b = bid >> 5, hw0 = (bid & 31) * 32;
    int tx = threadIdx.x & 31, ty = threadIdx.x >> 5;
    const float* xb = x + (size_t)b * 262144 + hw0 + tx;
#pragma unroll 8
    for (int g = 0; g < 32; g++) {
        int c = ty + g * 8;
        s[c][tx] = xb[(size_t)c * 1024];
    }
    __syncthreads();
    int wid = ty, lane = tx;
#pragma unroll
    for (int rr = 0; rr < 4; rr++) {
        int r = wid * 4 + rr;
        int n = b * 1024 + hw0 + r;
        double acc = 0.0;
#pragma unroll
        for (int j = 0; j < 8; j++) {
            int d = lane + j * 32;
            float v = s[d][r];
            acc += (double)v * v;
            g_XT[(size_t)n * 256 + d] = v;
            g_X1[(size_t)n * 256 + d] = __float2bfloat16(v);
        }
#pragma unroll
        for (int m = 16; m; m >>= 1) acc += __shfl_xor_sync(0xffffffffu, acc, m);
        if (lane == 0) g_xx[n] = (float)acc;
    }
}

// ======================= HMMA distance GEMM + in-CTA argmin ================
// M=64/CTA, 256 threads / 8 warps: warp_m = wid&1 (32 rows), warp_n = wid>>1
// smem ~100KB -> 2 CTAs/SM co-resident (cross-CTA latency hiding)
#define A_ROWS  64
#define A_PITCH 528
#define SM_B    33792                      // 64*528
#define B_PITCH 144
#define BSTG    18432
#define SM_ES   (SM_B + 3 * BSTG)          // 89088
#define SM_XS   (SM_ES + 4096)             // 93184
#define SM_RMIN (SM_XS + 256)              // 93440
#define SM_CCNT (SM_RMIN + 256)            // 93696
#define SM_CAND (SM_CCNT + 256)            // 93952
#define MAXCAND 32
#define DIST_SMEM (SM_CAND + A_ROWS * MAXCAND * 4)   // 102144
#define TAU 1e-3f

__device__ __forceinline__ void issue_b(uint32_t smem0, int stg, int t, int tid) {
    int nb = t >> 2, kc = t & 3;
    uint32_t dstb = smem0 + SM_B + stg * BSTG;
#pragma unroll
    for (int i = 0; i < 4; i++) {
        int idx = tid + i * 256;
        int r = idx >> 3, g = idx & 7;
        CP16(dstb + r * B_PITCH + g * 16,
             g_E1 + (size_t)(nb * 128 + r) * 256 + kc * 64 + g * 8);
    }
    CP_COMMIT();
}

__global__ void __launch_bounds__(256, 2) k_dist_mma(const float* __restrict__ cb) {
    extern __shared__ char smem[];
    float* es = (float*)(smem + SM_ES);
    float* xs = (float*)(smem + SM_XS);
    int* rowmin = (int*)(smem + SM_RMIN);
    int* ccnt = (int*)(smem + SM_CCNT);
    int* cand = (int*)(smem + SM_CAND);

    int tid = threadIdx.x, lane = tid & 31, wid = tid >> 5;
    int warp_m = wid & 1, warp_n = wid >> 1;
    int n0 = blockIdx.x * A_ROWS;
    uint32_t smem0 = smem_u32(smem);

    // A resident: 64 rows x 512B
#pragma unroll
    for (int i = 0; i < 8; i++) {
        int idx = tid + i * 256;
        int r = idx >> 5, g = idx & 31;
        CP16(smem0 + r * A_PITCH + g * 16, g_X1 + (size_t)(n0 + r) * 256 + g * 8);
    }
    CP_COMMIT();
    issue_b(smem0, 0, 0, tid);
    issue_b(smem0, 1, 1, tid);

    for (int i = tid; i < KCODES; i += 256) es[i] = g_ee[i];
    if (tid < A_ROWS) {
        xs[tid] = g_xx[n0 + tid];
        rowmin[tid] = 0x7F800000;   // +inf
        ccnt[tid] = 0;
    }

    uint32_t a_base = smem0 + (warp_m * 32 + (lane & 15)) * A_PITCH + (lane >> 4) * 16;
    uint32_t b_base = smem0 + SM_B + (warp_n * 32 + (lane & 7)) * B_PITCH + (lane >> 3) * 16;

    int gq = lane >> 2, iq = lane & 3;

    for (int nb = 0; nb < 8; nb++) {
        float acc[2][4][4];
#pragma unroll
        for (int mt = 0; mt < 2; mt++)
#pragma unroll
            for (int nt = 0; nt < 4; nt++)
#pragma unroll
                for (int q = 0; q < 4; q++) acc[mt][nt][q] = 0.0f;

        for (int kc = 0; kc < 4; kc++) {
            int t = nb * 4 + kc;
            if (t + 2 < 32) issue_b(smem0, (t + 2) % 3, t + 2, tid);
            if (t < 30)       asm volatile("cp.async.wait_group 2;" ::: "memory");
            else if (t == 30) asm volatile("cp.async.wait_group 1;" ::: "memory");
            else              asm volatile("cp.async.wait_group 0;" ::: "memory");
            __syncthreads();

            uint32_t bst = b_base + (t % 3) * BSTG;
            uint32_t ab = a_base + kc * 128;
#pragma unroll
            for (int kh = 0; kh < 2; kh++) {
                uint32_t bfr[4][4];
#pragma unroll
                for (int nt = 0; nt < 4; nt++)
                    LDSM4(bfr[nt], bst + nt * (8 * B_PITCH) + kh * 64);
#pragma unroll
                for (int ks = 0; ks < 2; ks++) {
                    uint32_t afr[2][4];
#pragma unroll
                    for (int mt = 0; mt < 2; mt++)
                        LDSM4(afr[mt], ab + mt * (16 * A_PITCH) + kh * 64 + ks * 32);
#pragma unroll
                    for (int mt = 0; mt < 2; mt++)
#pragma unroll
                        for (int nt = 0; nt < 4; nt++)
                            MMA16816(acc[mt][nt], afr[mt], bfr[nt][ks * 2], bfr[nt][ks * 2 + 1]);
                }
            }
            __syncthreads();
        }

        // ---- epilogue phase 1: per-row running min ----
#pragma unroll
        for (int mt = 0; mt < 2; mt++) {
#pragma unroll
            for (int h = 0; h < 2; h++) {
                int mrow = warp_m * 32 + mt * 16 + gq + h * 8;
                float xv = xs[mrow];
                float dmin = 3.4e38f;
#pragma unroll
                for (int nt = 0; nt < 4; nt++) {
                    int nbase = nb * 128 + warp_n * 32 + nt * 8 + 2 * iq;
                    float d0 = (xv + es[nbase])     - 2.0f * acc[mt][nt][h * 2 + 0];
                    float d1 = (xv + es[nbase + 1]) - 2.0f * acc[mt][nt][h * 2 + 1];
                    dmin = fminf(dmin, fminf(d0, d1));
                }
                atomicMin(&rowmin[mrow], __float_as_int(dmin));
            }
        }
        __syncthreads();
        // ---- epilogue phase 2: tight capture ----
#pragma unroll
        for (int mt = 0; mt < 2; mt++) {
#pragma unroll
            for (int h = 0; h < 2; h++) {
                int mrow = warp_m * 32 + mt * 16 + gq + h * 8;
                float xv = xs[mrow];
                float thr = __int_as_float(rowmin[mrow]) + TAU;
#pragma unroll
                for (int nt = 0; nt < 4; nt++) {
                    int nbase = nb * 128 + warp_n * 32 + nt * 8 + 2 * iq;
                    float d0 = (xv + es[nbase])     - 2.0f * acc[mt][nt][h * 2 + 0];
                    float d1 = (xv + es[nbase + 1]) - 2.0f * acc[mt][nt][h * 2 + 1];
                    if (d0 <= thr) {
                        int slot = atomicAdd(&ccnt[mrow], 1);
                        if (slot < MAXCAND) cand[mrow * MAXCAND + slot] = nbase;
                    }
                    if (d1 <= thr) {
                        int slot = atomicAdd(&ccnt[mrow], 1);
                        if (slot < MAXCAND) cand[mrow * MAXCAND + slot] = nbase + 1;
                    }
                }
            }
        }
    }
    __syncthreads();

    // exact fp32 rescore: warp w handles rows w*8..w*8+7
    for (int rr = 0; rr < 8; rr++) {
        int rl = wid * 8 + rr;
        int row = n0 + rl;
        int cnt = ccnt[rl];
        float xx = g_xx[row];
        const float4* xr4 = (const float4*)(g_XT + (size_t)row * 256 + lane * 8);
        float4 xa = xr4[0], xb4 = xr4[1];
        float best = 3.4e38f; int bidx = 0x7fffffff;
        bool overflow = (cnt > MAXCAND);
        int total = overflow ? KCODES : cnt;
        for (int c = 0; c < total; c++) {
            int k = overflow ? c : cand[rl * MAXCAND + c];
            const float4* cr = (const float4*)(cb + (size_t)k * 256 + lane * 8);
            float4 ca = cr[0], cbv = cr[1];
            float p = xa.x * ca.x;
            p = fmaf(xa.y, ca.y, p);
            p = fmaf(xa.z, ca.z, p);
            p = fmaf(xa.w, ca.w, p);
            p = fmaf(xb4.x, cbv.x, p);
            p = fmaf(xb4.y, cbv.y, p);
            p = fmaf(xb4.z, cbv.z, p);
            p = fmaf(xb4.w, cbv.w, p);
#pragma unroll
            for (int m = 16; m; m >>= 1) p += __shfl_xor_sync(0xffffffffu, p, m);
            float dd = (xx + es[k]) - 2.0f * p;
            if (dd < best || (dd == best && k < bidx)) { best = dd; bidx = k; }
        }
        if (lane == 0) g_idx[row] = bidx;
    }
}

// ======================= outputs ==========================================
__global__ void k_quant2(const float* __restrict__ x, const float* __restrict__ cb,
                         float* __restrict__ outq, int en) {
    __shared__ float xs[32][33];
    __shared__ float qs[32][33];
    __shared__ int ids[32];
    int bid = blockIdx.x;
    int b = bid >> 8, ct = (bid >> 5) & 7, ht = bid & 31;
    int tx = threadIdx.x & 31, ty = threadIdx.x >> 5;
    if (threadIdx.x < 32) ids[threadIdx.x] = g_idx[(b << 10) + ht * 32 + threadIdx.x];
#pragma unroll
    for (int r = 0; r < 4; r++)
        xs[ty + r * 8][tx] = x[(((size_t)b * 256 + ct * 32 + ty + r * 8) << 10) + ht * 32 + tx];
    __syncthreads();
#pragma unroll
    for (int r = 0; r < 4; r++) {
        int nl = ty + r * 8;
        qs[tx][nl] = cb[(size_t)ids[nl] * 256 + ct * 32 + tx];
    }
    __syncthreads();
    float local = 0.0f;
#pragma unroll
    for (int r = 0; r < 4; r++) {
        int cl = ty + r * 8;
        float in = xs[cl][tx];
        float q = qs[cl][tx];
        float diff = q - in;
        if (en) outq[(((size_t)b * 256 + ct * 32 + cl) << 10) + ht * 32 + tx] = in + diff;
        local = fmaf(diff, diff, local);
    }
    __shared__ float red[256];
    red[threadIdx.x] = local;
    __syncthreads();
    for (int sfr = 128; sfr; sfr >>= 1) {
        if (threadIdx.x < sfr) red[threadIdx.x] += red[threadIdx.x + sfr];
        __syncthreads();
    }
    if (threadIdx.x == 0) g_partial[bid] = red[0];
}

__global__ void k_loss(float* __restrict__ out_loss) {
    __shared__ float red[256];
    float s = 0.0f;
    int base = threadIdx.x * 32;
#pragma unroll
    for (int i = 0; i < 32; i++) s += g_partial[base + i];
    red[threadIdx.x] = s;
    __syncthreads();
    for (int t = 128; t; t >>= 1) {
        if (threadIdx.x < t) red[threadIdx.x] += red[threadIdx.x + t];
        __syncthreads();
    }
    if (threadIdx.x == 0) {
        float m = red[0] / 8388608.0f;
        out_loss[0] = m + 0.25f * m;
    }
}

// streaming zeros + one-hot + indices (SCALAR stores — slab 4B-aligned only)
__global__ void k_encodings(float* __restrict__ enc, float* __restrict__ outi,
                            int ee, int ei) {
    int n = blockIdx.x * 8 + (threadIdx.x >> 5);
    int lane = threadIdx.x & 31;
    int idx = g_idx[n];
    if (ee) {
        float* dst = enc + (size_t)n * 1024;
#pragma unroll
        for (int i = 0; i < 32; i++) {
            int j = lane + i * 32;
            dst[j] = (j == idx) ? 1.0f : 0.0f;
        }
    }
    if (ei && lane == 0) outi[n] = (float)idx;
}

// ===========================================================================
extern "C" void kernel_launch(void* const* d_in, const int* in_sizes, int n_in,
                              void* d_out, int out_size) {
    const float* x  = (const float*)d_in[0];
    const float* cb = (const float*)d_in[1];
    if (n_in >= 2 && in_sizes[0] == KCODES * DDIM && in_sizes[1] == (int)Q_ELEMS) {
        const float* t = x; x = cb; cb = t;
    }
    float* out = (float*)d_out;

    long long os = (long long)out_size;
    long long off_loss = -1, off_q = -1, off_e = -1, off_i = -1;
    if (os == 1 + Q_ELEMS + E_ELEMS + I_ELEMS) {
        off_loss = 0; off_q = 1; off_e = 1 + Q_ELEMS; off_i = 1 + Q_ELEMS + E_ELEMS;
    } else if (os == Q_ELEMS) {
        off_q = 0;
    } else if (os == 1) {
        off_loss = 0;
    } else if (os == 1 + Q_ELEMS) {
        off_loss = 0; off_q = 1;
    } else {
        if (os >= 1) off_loss = 0;
        if (os >= 1 + Q_ELEMS) off_q = 1;
        if (os >= 1 + Q_ELEMS + E_ELEMS) off_e = 1 + Q_ELEMS;
        if (os >= 1 + Q_ELEMS + E_ELEMS + I_ELEMS) off_i = 1 + Q_ELEMS + E_ELEMS;
    }

    cudaFuncSetAttribute(k_dist_mma, cudaFuncAttributeMaxDynamicSharedMemorySize, DIST_SMEM);

    k_prep_cb<<<128, 256>>>(cb);
    k_splitxx<<<1024, 256>>>(x);
    k_dist_mma<<<512, 256, DIST_SMEM>>>(cb);

    k_quant2<<<8192, 256>>>(x, cb,
                            (off_q >= 0) ? (out + off_q) : out,
                            (off_q >= 0) ? 1 : 0);
    if (off_loss >= 0) k_loss<<<1, 256>>>(out + off_loss);

    k_encodings<<<4096, 256>>>((off_e >= 0) ? (out + off_e) : out,
                               (off_i >= 0) ? (out + off_i) : out,
                               (off_e >= 0) ? 1 : 0,
                               (off_i >= 0) ? 1 : 0);
}